// round 3
// baseline (speedup 1.0000x reference)
#include <cuda_runtime.h>
#include <cstdint>

// Problem constants
#define EMB   1024
#define HEADS 16
#define HD    64
#define BATCH 4
#define SEQ   2048
#define MTOT  (BATCH * SEQ)          // 8192 rows
#define E3    (3 * EMB)              // 3072

// Scratch (static device globals — allocation-free per harness rules)
__device__ float g_qkv[(size_t)MTOT * E3];   // [B*S, 3E]  q|k|v concatenated
__device__ float g_ctx[(size_t)MTOT * EMB];  // [B*S, E]   attention output (head-interleaved)

// ---------------------------------------------------------------------------
// Tiled fp32 GEMM with bias:  C[M,N] = A[M,K] @ B[K,N] + bias[N]
// BM=BN=128, BK=16, 256 threads, 8x8 per thread, double-buffered smem.
// mode 0: A = Aext (x),    C = g_qkv
// mode 1: A = g_ctx,       C = Cext (d_out)
// ---------------------------------------------------------------------------
__global__ __launch_bounds__(256) void gemm_bias_kernel(
    const float* __restrict__ Aext, const float* __restrict__ B,
    const float* __restrict__ bias, float* __restrict__ Cext,
    int M, int N, int K, int mode)
{
    const float* A = (mode == 0) ? Aext : (const float*)g_ctx;
    float*       C = (mode == 0) ? (float*)g_qkv : Cext;

    __shared__ float As[2][16][128];   // transposed: As[buf][k][m]
    __shared__ float Bs[2][16][128];   // Bs[buf][k][n]

    const int tid = threadIdx.x;
    const int tx  = tid & 15;       // N direction
    const int ty  = tid >> 4;       // M direction
    const int m0  = blockIdx.y * 128;
    const int n0  = blockIdx.x * 128;

    const int a_r0 = (tid * 2) >> 2;
    const int a_c0 = ((tid * 2) & 3) * 4;
    const int a_r1 = (tid * 2 + 1) >> 2;
    const int a_c1 = ((tid * 2 + 1) & 3) * 4;
    const int b_r0 = (tid * 2) >> 5;
    const int b_c0 = ((tid * 2) & 31) * 4;
    const int b_r1 = (tid * 2 + 1) >> 5;
    const int b_c1 = ((tid * 2 + 1) & 31) * 4;

    float acc[8][8];
#pragma unroll
    for (int i = 0; i < 8; i++)
#pragma unroll
        for (int j = 0; j < 8; j++) acc[i][j] = 0.f;

    // Prologue: tile k0=0 -> buffer 0
    {
        float4 va0 = *(const float4*)(A + (size_t)(m0 + a_r0) * K + a_c0);
        float4 va1 = *(const float4*)(A + (size_t)(m0 + a_r1) * K + a_c1);
        As[0][a_c0 + 0][a_r0] = va0.x; As[0][a_c0 + 1][a_r0] = va0.y;
        As[0][a_c0 + 2][a_r0] = va0.z; As[0][a_c0 + 3][a_r0] = va0.w;
        As[0][a_c1 + 0][a_r1] = va1.x; As[0][a_c1 + 1][a_r1] = va1.y;
        As[0][a_c1 + 2][a_r1] = va1.z; As[0][a_c1 + 3][a_r1] = va1.w;
        *(float4*)&Bs[0][b_r0][b_c0] = *(const float4*)(B + (size_t)b_r0 * N + n0 + b_c0);
        *(float4*)&Bs[0][b_r1][b_c1] = *(const float4*)(B + (size_t)b_r1 * N + n0 + b_c1);
    }
    __syncthreads();

    int buf = 0;
    for (int k0 = 0; k0 < K; k0 += 16) {
        int nxt = buf ^ 1;
        if (k0 + 16 < K) {
            int kn = k0 + 16;
            float4 va0 = *(const float4*)(A + (size_t)(m0 + a_r0) * K + kn + a_c0);
            float4 va1 = *(const float4*)(A + (size_t)(m0 + a_r1) * K + kn + a_c1);
            float4 vb0 = *(const float4*)(B + (size_t)(kn + b_r0) * N + n0 + b_c0);
            float4 vb1 = *(const float4*)(B + (size_t)(kn + b_r1) * N + n0 + b_c1);
            As[nxt][a_c0 + 0][a_r0] = va0.x; As[nxt][a_c0 + 1][a_r0] = va0.y;
            As[nxt][a_c0 + 2][a_r0] = va0.z; As[nxt][a_c0 + 3][a_r0] = va0.w;
            As[nxt][a_c1 + 0][a_r1] = va1.x; As[nxt][a_c1 + 1][a_r1] = va1.y;
            As[nxt][a_c1 + 2][a_r1] = va1.z; As[nxt][a_c1 + 3][a_r1] = va1.w;
            *(float4*)&Bs[nxt][b_r0][b_c0] = vb0;
            *(float4*)&Bs[nxt][b_r1][b_c1] = vb1;
        }

#pragma unroll
        for (int kk = 0; kk < 16; kk++) {
            float4 a0 = *(float4*)&As[buf][kk][ty * 8];
            float4 a1 = *(float4*)&As[buf][kk][ty * 8 + 4];
            float4 b0 = *(float4*)&Bs[buf][kk][tx * 8];
            float4 b1 = *(float4*)&Bs[buf][kk][tx * 8 + 4];
            float av[8] = {a0.x, a0.y, a0.z, a0.w, a1.x, a1.y, a1.z, a1.w};
            float bv[8] = {b0.x, b0.y, b0.z, b0.w, b1.x, b1.y, b1.z, b1.w};
#pragma unroll
            for (int i = 0; i < 8; i++)
#pragma unroll
                for (int j = 0; j < 8; j++)
                    acc[i][j] = fmaf(av[i], bv[j], acc[i][j]);
        }
        __syncthreads();
        buf = nxt;
    }

    float4 bi0 = *(const float4*)(bias + n0 + tx * 8);
    float4 bi1 = *(const float4*)(bias + n0 + tx * 8 + 4);
    float bv[8] = {bi0.x, bi0.y, bi0.z, bi0.w, bi1.x, bi1.y, bi1.z, bi1.w};
#pragma unroll
    for (int i = 0; i < 8; i++) {
        size_t row = (size_t)(m0 + ty * 8 + i);
        float4 o0 = {acc[i][0] + bv[0], acc[i][1] + bv[1],
                     acc[i][2] + bv[2], acc[i][3] + bv[3]};
        float4 o1 = {acc[i][4] + bv[4], acc[i][5] + bv[5],
                     acc[i][6] + bv[6], acc[i][7] + bv[7]};
        *(float4*)(C + row * N + n0 + tx * 8)     = o0;
        *(float4*)(C + row * N + n0 + tx * 8 + 4) = o1;
    }
}

// ---------------------------------------------------------------------------
// Flash-attention fused softmax(QK^T/sqrt(D)) @ V, fp32, STATIC smem (<48KB).
// Block: (batch*head, 64-query tile). 256 threads as 16(tx) x 16(ty).
// Per key-tile of 32: thread owns 4q x 2k scores and 4q x 4d output.
// ---------------------------------------------------------------------------
#define KT 32

__global__ __launch_bounds__(256) void attn_kernel()
{
    __shared__ float QsT[64][68];   // [d][q]
    __shared__ float KsT[64][36];   // [d][k]
    __shared__ float Vs [KT][68];   // [k][d]
    __shared__ float Ps [64][36];   // [q][k]

    const int tid = threadIdx.x;
    const int tx  = tid & 15;
    const int ty  = tid >> 4;
    const int bh  = blockIdx.x;          // 0..63
    const int b   = bh >> 4;
    const int h   = bh & 15;
    const int q0  = blockIdx.y * 64;
    const size_t rowbase = (size_t)(b * SEQ) * E3;
    const int qoff = h * HD;
    const float* qkv = g_qkv;

    // Load Q tile (64 rows x 64 d), transposed into smem.
    for (int idx = tid; idx < 64 * 16; idx += 256) {
        int r = idx >> 4;
        int c = (idx & 15) << 2;
        float4 v = *(const float4*)(qkv + rowbase + (size_t)(q0 + r) * E3 + qoff + c);
        QsT[c + 0][r] = v.x;
        QsT[c + 1][r] = v.y;
        QsT[c + 2][r] = v.z;
        QsT[c + 3][r] = v.w;
    }

    float m[4], l[4], o[4][4];
#pragma unroll
    for (int i = 0; i < 4; i++) {
        m[i] = -1e30f;
        l[i] = 0.f;
#pragma unroll
        for (int j = 0; j < 4; j++) o[i][j] = 0.f;
    }

    for (int kt = 0; kt < SEQ / KT; kt++) {
        // Load K (transposed) and V tiles: KT rows x 64 d, 512 float4s, 2/thread.
        for (int idx = tid; idx < KT * 16; idx += 256) {
            int r = idx >> 4;
            int c = (idx & 15) << 2;
            const float* src = qkv + rowbase + (size_t)(kt * KT + r) * E3 + qoff;
            float4 kv = *(const float4*)(src + EMB + c);
            KsT[c + 0][r] = kv.x;
            KsT[c + 1][r] = kv.y;
            KsT[c + 2][r] = kv.z;
            KsT[c + 3][r] = kv.w;
            *(float4*)&Vs[r][c] = *(const float4*)(src + 2 * EMB + c);
        }
        __syncthreads();

        // Scores: s[i][j] = sum_d Q[q_i][d] * K[k_j][d]   (4q x 2k per thread)
        float s[4][2];
#pragma unroll
        for (int i = 0; i < 4; i++) { s[i][0] = 0.f; s[i][1] = 0.f; }

#pragma unroll 8
        for (int d = 0; d < 64; d++) {
            float4 qv = *(float4*)&QsT[d][ty * 4];
            float2 kv = *(float2*)&KsT[d][tx * 2];
            float qa[4] = {qv.x, qv.y, qv.z, qv.w};
#pragma unroll
            for (int i = 0; i < 4; i++) {
                s[i][0] = fmaf(qa[i], kv.x, s[i][0]);
                s[i][1] = fmaf(qa[i], kv.y, s[i][1]);
            }
        }

        // Online softmax (row shared across 16 lanes of a half-warp)
#pragma unroll
        for (int i = 0; i < 4; i++) {
            s[i][0] *= 0.125f;   // 1/sqrt(64)
            s[i][1] *= 0.125f;

            float tmax = fmaxf(s[i][0], s[i][1]);
#pragma unroll
            for (int off = 8; off >= 1; off >>= 1)
                tmax = fmaxf(tmax, __shfl_xor_sync(0xffffffffu, tmax, off));

            float mn = fmaxf(m[i], tmax);
            float alpha = __expf(m[i] - mn);
            float p0 = __expf(s[i][0] - mn);
            float p1 = __expf(s[i][1] - mn);
            Ps[ty * 4 + i][tx * 2 + 0] = p0;
            Ps[ty * 4 + i][tx * 2 + 1] = p1;
            float rsum = p0 + p1;
#pragma unroll
            for (int off = 8; off >= 1; off >>= 1)
                rsum += __shfl_xor_sync(0xffffffffu, rsum, off);

            l[i] = l[i] * alpha + rsum;
            m[i] = mn;
#pragma unroll
            for (int j = 0; j < 4; j++) o[i][j] *= alpha;
        }
        __syncthreads();

        // O += P @ V
#pragma unroll 8
        for (int k = 0; k < KT; k++) {
            float4 vv = *(float4*)&Vs[k][tx * 4];
            float va[4] = {vv.x, vv.y, vv.z, vv.w};
#pragma unroll
            for (int i = 0; i < 4; i++) {
                float p = Ps[ty * 4 + i][k];
#pragma unroll
                for (int j = 0; j < 4; j++)
                    o[i][j] = fmaf(p, va[j], o[i][j]);
            }
        }
        __syncthreads();   // before next tile overwrites KsT/Vs/Ps
    }

    // Normalize, write ctx [B*S, E] head-interleaved.
#pragma unroll
    for (int i = 0; i < 4; i++) {
        float inv = 1.0f / l[i];
        float4 out = {o[i][0] * inv, o[i][1] * inv, o[i][2] * inv, o[i][3] * inv};
        size_t row = (size_t)(b * SEQ + q0 + ty * 4 + i);
        *(float4*)(g_ctx + row * EMB + qoff + tx * 4) = out;
    }
}

// ---------------------------------------------------------------------------
// Launch: pure kernel launches, no runtime API calls (graph-capture safe).
// ---------------------------------------------------------------------------
extern "C" void kernel_launch(void* const* d_in, const int* in_sizes, int n_in,
                              void* d_out, int out_size)
{
    const float* x     = (const float*)d_in[0];
    const float* W_qkv = (const float*)d_in[1];
    const float* b_qkv = (const float*)d_in[2];
    const float* W_o   = (const float*)d_in[3];
    const float* b_o   = (const float*)d_in[4];
    float* out = (float*)d_out;

    // 1) QKV projection: [8192,1024] @ [1024,3072] + b -> g_qkv
    gemm_bias_kernel<<<dim3(E3 / 128, MTOT / 128), 256>>>(
        x, W_qkv, b_qkv, nullptr, MTOT, E3, EMB, 0);

    // 2) Fused attention per (b,h), online softmax -> g_ctx
    attn_kernel<<<dim3(BATCH * HEADS, SEQ / 64), 256>>>();

    // 3) Output projection: [8192,1024] @ [1024,1024] + b -> d_out
    gemm_bias_kernel<<<dim3(EMB / 128, MTOT / 128), 256>>>(
        nullptr, W_o, b_o, out, MTOT, EMB, EMB, 1);
}

// round 5
// speedup vs baseline: 1.2343x; 1.2343x over previous
#include <cuda_runtime.h>
#include <cuda_bf16.h>
#include <cstdint>

// Problem constants
#define EMB   1024
#define HEADS 16
#define HD    64
#define BATCH 4
#define SEQ   2048
#define MTOT  (BATCH * SEQ)          // 8192 rows
#define E3    (3 * EMB)              // 3072

// ---------------------------------------------------------------------------
// Scratch (static device globals — allocation-free per harness rules)
// ---------------------------------------------------------------------------
__device__ float g_qkv[(size_t)MTOT * E3];   // [B*S, 3E]  q|k|v
__device__ float g_ctx[(size_t)MTOT * EMB];  // [B*S, E]   attention output
__device__ __nv_bfloat16 g_a_hi[(size_t)MTOT * EMB];   // split of x / ctx
__device__ __nv_bfloat16 g_a_lo[(size_t)MTOT * EMB];
__device__ __nv_bfloat16 g_wq_hi[(size_t)E3 * EMB];    // W_qkv^T split [N,K]
__device__ __nv_bfloat16 g_wq_lo[(size_t)E3 * EMB];
__device__ __nv_bfloat16 g_wo_hi[(size_t)EMB * EMB];   // W_o^T split [N,K]
__device__ __nv_bfloat16 g_wo_lo[(size_t)EMB * EMB];

// ---------------------------------------------------------------------------
// sm_80+ tensor-core primitives (legal on plain sm_100 target)
// ---------------------------------------------------------------------------
__device__ __forceinline__ uint32_t smem_u32(const void* p) {
    uint32_t a;
    asm("{ .reg .u64 t; cvta.to.shared.u64 t, %1; cvt.u32.u64 %0, t; }"
        : "=r"(a) : "l"(p));
    return a;
}

__device__ __forceinline__ void ldmx4(uint32_t* r, uint32_t addr) {
    asm volatile("ldmatrix.sync.aligned.m8n8.x4.shared.b16 {%0,%1,%2,%3}, [%4];"
                 : "=r"(r[0]), "=r"(r[1]), "=r"(r[2]), "=r"(r[3]) : "r"(addr));
}

__device__ __forceinline__ void mma_bf16(float* d, const uint32_t* a,
                                         uint32_t b0, uint32_t b1) {
    asm volatile(
        "mma.sync.aligned.m16n8k16.row.col.f32.bf16.bf16.f32 "
        "{%0,%1,%2,%3}, {%4,%5,%6,%7}, {%8,%9}, {%0,%1,%2,%3};"
        : "+f"(d[0]), "+f"(d[1]), "+f"(d[2]), "+f"(d[3])
        : "r"(a[0]), "r"(a[1]), "r"(a[2]), "r"(a[3]), "r"(b0), "r"(b1));
}

// ---------------------------------------------------------------------------
// Preprocessing: elementwise hi/lo bf16 split. mode 0: X=xext, mode 1: X=g_ctx
// ---------------------------------------------------------------------------
__global__ __launch_bounds__(256) void split_kernel(const float* __restrict__ Xext,
                                                    int mode, size_t n4)
{
    size_t i = (size_t)blockIdx.x * blockDim.x + threadIdx.x;
    if (i >= n4) return;
    const float* X = (mode == 0) ? Xext : (const float*)g_ctx;
    float4 v = ((const float4*)X)[i];
    __nv_bfloat16 h0 = __float2bfloat16(v.x);
    __nv_bfloat16 h1 = __float2bfloat16(v.y);
    __nv_bfloat16 h2 = __float2bfloat16(v.z);
    __nv_bfloat16 h3 = __float2bfloat16(v.w);
    __nv_bfloat162 H01; H01.x = h0; H01.y = h1;
    __nv_bfloat162 H23; H23.x = h2; H23.y = h3;
    __nv_bfloat162 L01;
    L01.x = __float2bfloat16(v.x - __bfloat162float(h0));
    L01.y = __float2bfloat16(v.y - __bfloat162float(h1));
    __nv_bfloat162 L23;
    L23.x = __float2bfloat16(v.z - __bfloat162float(h2));
    L23.y = __float2bfloat16(v.w - __bfloat162float(h3));
    *(__nv_bfloat162*)(g_a_hi + i * 4)     = H01;
    *(__nv_bfloat162*)(g_a_hi + i * 4 + 2) = H23;
    *(__nv_bfloat162*)(g_a_lo + i * 4)     = L01;
    *(__nv_bfloat162*)(g_a_lo + i * 4 + 2) = L23;
}

// ---------------------------------------------------------------------------
// Preprocessing: W [K,N] fp32 -> W^T hi/lo bf16 [N,K]. mode 0: g_wq, 1: g_wo
// ---------------------------------------------------------------------------
__global__ __launch_bounds__(256) void transpose_split_kernel(
    const float* __restrict__ W, int mode, int K, int N)
{
    __shared__ float t[32][33];
    const int n0 = blockIdx.x * 32, k0 = blockIdx.y * 32;
    const int tx = threadIdx.x, ty = threadIdx.y;
    for (int i = ty; i < 32; i += 8)
        t[i][tx] = W[(size_t)(k0 + i) * N + n0 + tx];
    __syncthreads();
    __nv_bfloat16* Th = mode ? g_wo_hi : g_wq_hi;
    __nv_bfloat16* Tl = mode ? g_wo_lo : g_wq_lo;
    for (int i = ty; i < 32; i += 8) {
        float v = t[tx][i];                    // = W[k0+tx][n0+i]
        __nv_bfloat16 h = __float2bfloat16(v);
        size_t o = (size_t)(n0 + i) * K + k0 + tx;
        Th[o] = h;
        Tl[o] = __float2bfloat16(v - __bfloat162float(h));
    }
}

// ---------------------------------------------------------------------------
// Tensor-core bf16 3-term-split GEMM: C[M,N] = A[M,K]@B^T[N,K] + bias
// mma.sync m16n8k16. Block 128x128, BK=32, 8 warps (2m x 4n), warp 64x32.
// 96 k-iters = 3 segments (Ah*Bh, Ah*Bl, Al*Bh) x 32.
// mode 0: C = g_qkv (N=3072); mode 1: C = Cext (N=1024)
// ---------------------------------------------------------------------------
#define BK      32
#define AS_STR  40                       // row stride in bf16 (80B, conflict-free)
#define TILE_E  (128 * AS_STR)           // elements per stage

__global__ __launch_bounds__(256) void tgemm_mma(
    const float* __restrict__ bias, float* __restrict__ Cext, int N, int mode)
{
    __shared__ alignas(16) __nv_bfloat16 As[2][TILE_E];
    __shared__ alignas(16) __nv_bfloat16 Bs[2][TILE_E];

    const int tid  = threadIdx.x;
    const int wid  = tid >> 5;
    const int lane = tid & 31;
    const int wm   = wid & 1;            // 0..1 : 64-row half
    const int wn   = wid >> 1;           // 0..3 : 32-col quarter
    const int m0   = blockIdx.y * 128;
    const int n0   = blockIdx.x * 128;
    const int K    = EMB;
    const int NIT  = 96;                 // 3 * (K / BK)

    const __nv_bfloat16* Bh = mode ? g_wo_hi : g_wq_hi;
    const __nv_bfloat16* Bl = mode ? g_wo_lo : g_wq_lo;
    float* C = mode ? Cext : (float*)g_qkv;

    float acc[4][4][4];
#pragma unroll
    for (int i = 0; i < 4; i++)
#pragma unroll
        for (int j = 0; j < 4; j++)
#pragma unroll
            for (int k = 0; k < 4; k++) acc[i][j][k] = 0.f;

    // Global-load coords: 512 float4 per tile, 2 per thread.
    const int r0 = (tid * 2) >> 2,     c0 = ((tid * 2) & 3) * 8;
    const int r1 = (tid * 2 + 1) >> 2, c1 = ((tid * 2 + 1) & 3) * 8;

    // ldmatrix lane addressing
    const int a_lrow  = lane & 15;              // + wm*64 + mf*16
    const int a_lcol  = (lane >> 4) * 8;        // + k8
    const int b_lrow  = (lane & 7) + ((lane >> 4) << 3);  // + wn*32 + nf2*16
    const int b_lcol  = ((lane >> 3) & 1) * 8;  // + k8

    const uint32_t sA = smem_u32(As);
    const uint32_t sB = smem_u32(Bs);

    // Prologue: tile 0 (segment 0: Ah, Bh) -> buffer 0
    {
        *(float4*)&As[0][r0 * AS_STR + c0] =
            *(const float4*)(g_a_hi + (size_t)(m0 + r0) * K + c0);
        *(float4*)&As[0][r1 * AS_STR + c1] =
            *(const float4*)(g_a_hi + (size_t)(m0 + r1) * K + c1);
        *(float4*)&Bs[0][r0 * AS_STR + c0] =
            *(const float4*)(Bh + (size_t)(n0 + r0) * K + c0);
        *(float4*)&Bs[0][r1 * AS_STR + c1] =
            *(const float4*)(Bh + (size_t)(n0 + r1) * K + c1);
    }
    __syncthreads();

    int buf = 0;
    for (int it = 0; it < NIT; it++) {
        // Prefetch next tile into registers
        float4 pa0, pa1, pb0, pb1;
        if (it + 1 < NIT) {
            const int nit = it + 1;
            const int seg = nit >> 5;
            const int kk  = (nit & 31) * BK;
            const __nv_bfloat16* Ap = (seg < 2)  ? g_a_hi : g_a_lo;
            const __nv_bfloat16* Bp = (seg == 1) ? Bl : Bh;
            pa0 = *(const float4*)(Ap + (size_t)(m0 + r0) * K + kk + c0);
            pa1 = *(const float4*)(Ap + (size_t)(m0 + r1) * K + kk + c1);
            pb0 = *(const float4*)(Bp + (size_t)(n0 + r0) * K + kk + c0);
            pb1 = *(const float4*)(Bp + (size_t)(n0 + r1) * K + kk + c1);
        }

        // Compute on current buffer: 2 k-steps of 16
        const uint32_t baseA = sA + (uint32_t)buf * (TILE_E * 2);
        const uint32_t baseB = sB + (uint32_t)buf * (TILE_E * 2);
#pragma unroll
        for (int ks = 0; ks < 2; ks++) {
            const int k8 = ks * 16;
            uint32_t a[4][4];
#pragma unroll
            for (int mf = 0; mf < 4; mf++) {
                uint32_t addr = baseA +
                    ((uint32_t)((wm * 64 + mf * 16 + a_lrow) * AS_STR
                                + k8 + a_lcol) << 1);
                ldmx4(a[mf], addr);
            }
            uint32_t b[2][4];
#pragma unroll
            for (int nf2 = 0; nf2 < 2; nf2++) {
                uint32_t addr = baseB +
                    ((uint32_t)((wn * 32 + nf2 * 16 + b_lrow) * AS_STR
                                + k8 + b_lcol) << 1);
                ldmx4(b[nf2], addr);
            }
#pragma unroll
            for (int mf = 0; mf < 4; mf++) {
#pragma unroll
                for (int nf = 0; nf < 4; nf++) {
                    uint32_t b0 = b[nf >> 1][(nf & 1) * 2];
                    uint32_t b1 = b[nf >> 1][(nf & 1) * 2 + 1];
                    mma_bf16(acc[mf][nf], a[mf], b0, b1);
                }
            }
        }

        // Store prefetched tile into the other buffer
        if (it + 1 < NIT) {
            int nb = buf ^ 1;
            *(float4*)&As[nb][r0 * AS_STR + c0] = pa0;
            *(float4*)&As[nb][r1 * AS_STR + c1] = pa1;
            *(float4*)&Bs[nb][r0 * AS_STR + c0] = pb0;
            *(float4*)&Bs[nb][r1 * AS_STR + c1] = pb1;
        }
        __syncthreads();
        buf ^= 1;
    }

    // Epilogue: c frag mapping for m16n8 f32: {c0,c1} row lane/4, cols 2*(lane%4);
    // {c2,c3} row+8.
#pragma unroll
    for (int mf = 0; mf < 4; mf++) {
        const int r = m0 + wm * 64 + mf * 16 + (lane >> 2);
#pragma unroll
        for (int nf = 0; nf < 4; nf++) {
            const int c = n0 + wn * 32 + nf * 8 + (lane & 3) * 2;
            const float b0 = bias[c], b1 = bias[c + 1];
            float2 lo = make_float2(acc[mf][nf][0] + b0, acc[mf][nf][1] + b1);
            float2 hi = make_float2(acc[mf][nf][2] + b0, acc[mf][nf][3] + b1);
            *(float2*)&C[(size_t)r * N + c]       = lo;
            *(float2*)&C[(size_t)(r + 8) * N + c] = hi;
        }
    }
}

// ---------------------------------------------------------------------------
// Flash-attention fused softmax(QK^T/sqrt(D)) @ V, fp32, static smem (<48KB).
// (unchanged from the passing round-3 kernel)
// ---------------------------------------------------------------------------
#define KT 32

__global__ __launch_bounds__(256) void attn_kernel()
{
    __shared__ float QsT[64][68];   // [d][q]
    __shared__ float KsT[64][36];   // [d][k]
    __shared__ float Vs [KT][68];   // [k][d]
    __shared__ float Ps [64][36];   // [q][k]

    const int tid = threadIdx.x;
    const int tx  = tid & 15;
    const int ty  = tid >> 4;
    const int bh  = blockIdx.x;          // 0..63
    const int b   = bh >> 4;
    const int h   = bh & 15;
    const int q0  = blockIdx.y * 64;
    const size_t rowbase = (size_t)(b * SEQ) * E3;
    const int qoff = h * HD;
    const float* qkv = g_qkv;

    for (int idx = tid; idx < 64 * 16; idx += 256) {
        int r = idx >> 4;
        int c = (idx & 15) << 2;
        float4 v = *(const float4*)(qkv + rowbase + (size_t)(q0 + r) * E3 + qoff + c);
        QsT[c + 0][r] = v.x;
        QsT[c + 1][r] = v.y;
        QsT[c + 2][r] = v.z;
        QsT[c + 3][r] = v.w;
    }

    float m[4], l[4], o[4][4];
#pragma unroll
    for (int i = 0; i < 4; i++) {
        m[i] = -1e30f;
        l[i] = 0.f;
#pragma unroll
        for (int j = 0; j < 4; j++) o[i][j] = 0.f;
    }

    for (int kt = 0; kt < SEQ / KT; kt++) {
        for (int idx = tid; idx < KT * 16; idx += 256) {
            int r = idx >> 4;
            int c = (idx & 15) << 2;
            const float* src = qkv + rowbase + (size_t)(kt * KT + r) * E3 + qoff;
            float4 kv = *(const float4*)(src + EMB + c);
            KsT[c + 0][r] = kv.x;
            KsT[c + 1][r] = kv.y;
            KsT[c + 2][r] = kv.z;
            KsT[c + 3][r] = kv.w;
            *(float4*)&Vs[r][c] = *(const float4*)(src + 2 * EMB + c);
        }
        __syncthreads();

        float s[4][2];
#pragma unroll
        for (int i = 0; i < 4; i++) { s[i][0] = 0.f; s[i][1] = 0.f; }

#pragma unroll 8
        for (int d = 0; d < 64; d++) {
            float4 qv = *(float4*)&QsT[d][ty * 4];
            float2 kv = *(float2*)&KsT[d][tx * 2];
            float qa[4] = {qv.x, qv.y, qv.z, qv.w};
#pragma unroll
            for (int i = 0; i < 4; i++) {
                s[i][0] = fmaf(qa[i], kv.x, s[i][0]);
                s[i][1] = fmaf(qa[i], kv.y, s[i][1]);
            }
        }

#pragma unroll
        for (int i = 0; i < 4; i++) {
            s[i][0] *= 0.125f;
            s[i][1] *= 0.125f;

            float tmax = fmaxf(s[i][0], s[i][1]);
#pragma unroll
            for (int off = 8; off >= 1; off >>= 1)
                tmax = fmaxf(tmax, __shfl_xor_sync(0xffffffffu, tmax, off));

            float mn = fmaxf(m[i], tmax);
            float alpha = __expf(m[i] - mn);
            float p0 = __expf(s[i][0] - mn);
            float p1 = __expf(s[i][1] - mn);
            Ps[ty * 4 + i][tx * 2 + 0] = p0;
            Ps[ty * 4 + i][tx * 2 + 1] = p1;
            float rsum = p0 + p1;
#pragma unroll
            for (int off = 8; off >= 1; off >>= 1)
                rsum += __shfl_xor_sync(0xffffffffu, rsum, off);

            l[i] = l[i] * alpha + rsum;
            m[i] = mn;
#pragma unroll
            for (int j = 0; j < 4; j++) o[i][j] *= alpha;
        }
        __syncthreads();

#pragma unroll 8
        for (int k = 0; k < KT; k++) {
            float4 vv = *(float4*)&Vs[k][tx * 4];
            float va[4] = {vv.x, vv.y, vv.z, vv.w};
#pragma unroll
            for (int i = 0; i < 4; i++) {
                float p = Ps[ty * 4 + i][k];
#pragma unroll
                for (int j = 0; j < 4; j++)
                    o[i][j] = fmaf(p, va[j], o[i][j]);
            }
        }
        __syncthreads();
    }

#pragma unroll
    for (int i = 0; i < 4; i++) {
        float inv = 1.0f / l[i];
        float4 out = {o[i][0] * inv, o[i][1] * inv, o[i][2] * inv, o[i][3] * inv};
        size_t row = (size_t)(b * SEQ + q0 + ty * 4 + i);
        *(float4*)(g_ctx + row * EMB + qoff + tx * 4) = out;
    }
}

// ---------------------------------------------------------------------------
// Launch: pure kernel launches (graph-capture safe, no runtime API calls).
// ---------------------------------------------------------------------------
extern "C" void kernel_launch(void* const* d_in, const int* in_sizes, int n_in,
                              void* d_out, int out_size)
{
    const float* x     = (const float*)d_in[0];
    const float* W_qkv = (const float*)d_in[1];
    const float* b_qkv = (const float*)d_in[2];
    const float* W_o   = (const float*)d_in[3];
    const float* b_o   = (const float*)d_in[4];
    float* out = (float*)d_out;

    const size_t n4 = (size_t)MTOT * EMB / 4;

    // Preprocess: split x, transpose+split weights
    split_kernel<<<(unsigned)((n4 + 255) / 256), 256>>>(x, 0, n4);
    transpose_split_kernel<<<dim3(E3 / 32, EMB / 32), dim3(32, 8)>>>(W_qkv, 0, EMB, E3);
    transpose_split_kernel<<<dim3(EMB / 32, EMB / 32), dim3(32, 8)>>>(W_o, 1, EMB, EMB);

    // 1) QKV projection on tensor cores -> g_qkv
    tgemm_mma<<<dim3(E3 / 128, MTOT / 128), 256>>>(b_qkv, nullptr, E3, 0);

    // 2) Fused attention -> g_ctx
    attn_kernel<<<dim3(BATCH * HEADS, SEQ / 64), 256>>>();

    // 3) Split ctx, output projection on tensor cores -> d_out
    split_kernel<<<(unsigned)((n4 + 255) / 256), 256>>>(nullptr, 1, n4);
    tgemm_mma<<<dim3(EMB / 128, MTOT / 128), 256>>>(b_o, out, EMB, 1);
}

// round 6
// speedup vs baseline: 2.7331x; 2.2144x over previous
#include <cuda_runtime.h>
#include <cuda_bf16.h>
#include <cstdint>

// Problem constants
#define EMB   1024
#define HEADS 16
#define HD    64
#define BATCH 4
#define SEQ   2048
#define MTOT  (BATCH * SEQ)          // 8192 rows
#define E3    (3 * EMB)              // 3072

// ---------------------------------------------------------------------------
// Scratch (static device globals — allocation-free per harness rules)
// ---------------------------------------------------------------------------
__device__ float g_qkv[(size_t)MTOT * E3];   // [B*S, 3E]  q|k|v (fp32)
__device__ float g_ctx[(size_t)MTOT * EMB];  // [B*S, E]   attention output
__device__ __nv_bfloat16 g_a_hi[(size_t)MTOT * EMB];   // split of x / ctx
__device__ __nv_bfloat16 g_a_lo[(size_t)MTOT * EMB];
__device__ __nv_bfloat16 g_wq_hi[(size_t)E3 * EMB];    // W_qkv^T split [N,K]
__device__ __nv_bfloat16 g_wq_lo[(size_t)E3 * EMB];
__device__ __nv_bfloat16 g_wo_hi[(size_t)EMB * EMB];   // W_o^T split [N,K]
__device__ __nv_bfloat16 g_wo_lo[(size_t)EMB * EMB];
// attention operands (bf16)
__device__ __nv_bfloat16 g_q_hi[(size_t)MTOT * EMB];   // Q*0.125 hi
__device__ __nv_bfloat16 g_q_lo[(size_t)MTOT * EMB];   // Q*0.125 lo
__device__ __nv_bfloat16 g_k_hi[(size_t)MTOT * EMB];
__device__ __nv_bfloat16 g_k_lo[(size_t)MTOT * EMB];
__device__ __nv_bfloat16 g_v  [(size_t)MTOT * EMB];

// ---------------------------------------------------------------------------
// sm_80+ tensor-core primitives (legal on plain sm_100 target)
// ---------------------------------------------------------------------------
__device__ __forceinline__ uint32_t smem_u32(const void* p) {
    uint32_t a;
    asm("{ .reg .u64 t; cvta.to.shared.u64 t, %1; cvt.u32.u64 %0, t; }"
        : "=r"(a) : "l"(p));
    return a;
}

__device__ __forceinline__ void ldmx4(uint32_t* r, uint32_t addr) {
    asm volatile("ldmatrix.sync.aligned.m8n8.x4.shared.b16 {%0,%1,%2,%3}, [%4];"
                 : "=r"(r[0]), "=r"(r[1]), "=r"(r[2]), "=r"(r[3]) : "r"(addr));
}

__device__ __forceinline__ void ldmx4t(uint32_t* r, uint32_t addr) {
    asm volatile("ldmatrix.sync.aligned.m8n8.x4.trans.shared.b16 {%0,%1,%2,%3}, [%4];"
                 : "=r"(r[0]), "=r"(r[1]), "=r"(r[2]), "=r"(r[3]) : "r"(addr));
}

__device__ __forceinline__ void mma_bf16(float* d, const uint32_t* a,
                                         uint32_t b0, uint32_t b1) {
    asm volatile(
        "mma.sync.aligned.m16n8k16.row.col.f32.bf16.bf16.f32 "
        "{%0,%1,%2,%3}, {%4,%5,%6,%7}, {%8,%9}, {%0,%1,%2,%3};"
        : "+f"(d[0]), "+f"(d[1]), "+f"(d[2]), "+f"(d[3])
        : "r"(a[0]), "r"(a[1]), "r"(a[2]), "r"(a[3]), "r"(b0), "r"(b1));
}

__device__ __forceinline__ uint32_t pack_bf16x2(float lo, float hi) {
    __nv_bfloat162 p = __float22bfloat162_rn(make_float2(lo, hi));
    return *(uint32_t*)&p;
}

// ---------------------------------------------------------------------------
// Preprocessing: elementwise hi/lo bf16 split. mode 0: X=xext, mode 1: X=g_ctx
// ---------------------------------------------------------------------------
__global__ __launch_bounds__(256) void split_kernel(const float* __restrict__ Xext,
                                                    int mode, size_t n4)
{
    size_t i = (size_t)blockIdx.x * blockDim.x + threadIdx.x;
    if (i >= n4) return;
    const float* X = (mode == 0) ? Xext : (const float*)g_ctx;
    float4 v = ((const float4*)X)[i];
    __nv_bfloat16 h0 = __float2bfloat16(v.x);
    __nv_bfloat16 h1 = __float2bfloat16(v.y);
    __nv_bfloat16 h2 = __float2bfloat16(v.z);
    __nv_bfloat16 h3 = __float2bfloat16(v.w);
    __nv_bfloat162 H01; H01.x = h0; H01.y = h1;
    __nv_bfloat162 H23; H23.x = h2; H23.y = h3;
    __nv_bfloat162 L01;
    L01.x = __float2bfloat16(v.x - __bfloat162float(h0));
    L01.y = __float2bfloat16(v.y - __bfloat162float(h1));
    __nv_bfloat162 L23;
    L23.x = __float2bfloat16(v.z - __bfloat162float(h2));
    L23.y = __float2bfloat16(v.w - __bfloat162float(h3));
    *(__nv_bfloat162*)(g_a_hi + i * 4)     = H01;
    *(__nv_bfloat162*)(g_a_hi + i * 4 + 2) = H23;
    *(__nv_bfloat162*)(g_a_lo + i * 4)     = L01;
    *(__nv_bfloat162*)(g_a_lo + i * 4 + 2) = L23;
}

// ---------------------------------------------------------------------------
// Preprocessing: W [K,N] fp32 -> W^T hi/lo bf16 [N,K]. mode 0: g_wq, 1: g_wo
// ---------------------------------------------------------------------------
__global__ __launch_bounds__(256) void transpose_split_kernel(
    const float* __restrict__ W, int mode, int K, int N)
{
    __shared__ float t[32][33];
    const int n0 = blockIdx.x * 32, k0 = blockIdx.y * 32;
    const int tx = threadIdx.x, ty = threadIdx.y;
    for (int i = ty; i < 32; i += 8)
        t[i][tx] = W[(size_t)(k0 + i) * N + n0 + tx];
    __syncthreads();
    __nv_bfloat16* Th = mode ? g_wo_hi : g_wq_hi;
    __nv_bfloat16* Tl = mode ? g_wo_lo : g_wq_lo;
    for (int i = ty; i < 32; i += 8) {
        float v = t[tx][i];                    // = W[k0+tx][n0+i]
        __nv_bfloat16 h = __float2bfloat16(v);
        size_t o = (size_t)(n0 + i) * K + k0 + tx;
        Th[o] = h;
        Tl[o] = __float2bfloat16(v - __bfloat162float(h));
    }
}

// ---------------------------------------------------------------------------
// Convert g_qkv (fp32) -> bf16 attention operands.
// Q scaled by 0.125 (folds 1/sqrt(64)) then hi/lo split; K hi/lo; V plain.
// One thread per 4 elements of the [MTOT x EMB] section.
// ---------------------------------------------------------------------------
__global__ __launch_bounds__(256) void qkv_convert_kernel()
{
    size_t i = (size_t)blockIdx.x * blockDim.x + threadIdx.x;
    if (i >= (size_t)MTOT * EMB / 4) return;
    size_t row = i >> 8;                 // EMB/4 = 256 groups per row
    size_t c4  = (i & 255) * 4;
    const float* base = g_qkv + row * E3;
    size_t o = row * EMB + c4;

    // Q (scaled)
    {
        float4 v = *(const float4*)(base + c4);
        v.x *= 0.125f; v.y *= 0.125f; v.z *= 0.125f; v.w *= 0.125f;
        __nv_bfloat16 h0 = __float2bfloat16(v.x), h1 = __float2bfloat16(v.y);
        __nv_bfloat16 h2 = __float2bfloat16(v.z), h3 = __float2bfloat16(v.w);
        __nv_bfloat162 H01; H01.x = h0; H01.y = h1;
        __nv_bfloat162 H23; H23.x = h2; H23.y = h3;
        __nv_bfloat162 L01, L23;
        L01.x = __float2bfloat16(v.x - __bfloat162float(h0));
        L01.y = __float2bfloat16(v.y - __bfloat162float(h1));
        L23.x = __float2bfloat16(v.z - __bfloat162float(h2));
        L23.y = __float2bfloat16(v.w - __bfloat162float(h3));
        *(__nv_bfloat162*)(g_q_hi + o)     = H01;
        *(__nv_bfloat162*)(g_q_hi + o + 2) = H23;
        *(__nv_bfloat162*)(g_q_lo + o)     = L01;
        *(__nv_bfloat162*)(g_q_lo + o + 2) = L23;
    }
    // K
    {
        float4 v = *(const float4*)(base + EMB + c4);
        __nv_bfloat16 h0 = __float2bfloat16(v.x), h1 = __float2bfloat16(v.y);
        __nv_bfloat16 h2 = __float2bfloat16(v.z), h3 = __float2bfloat16(v.w);
        __nv_bfloat162 H01; H01.x = h0; H01.y = h1;
        __nv_bfloat162 H23; H23.x = h2; H23.y = h3;
        __nv_bfloat162 L01, L23;
        L01.x = __float2bfloat16(v.x - __bfloat162float(h0));
        L01.y = __float2bfloat16(v.y - __bfloat162float(h1));
        L23.x = __float2bfloat16(v.z - __bfloat162float(h2));
        L23.y = __float2bfloat16(v.w - __bfloat162float(h3));
        *(__nv_bfloat162*)(g_k_hi + o)     = H01;
        *(__nv_bfloat162*)(g_k_hi + o + 2) = H23;
        *(__nv_bfloat162*)(g_k_lo + o)     = L01;
        *(__nv_bfloat162*)(g_k_lo + o + 2) = L23;
    }
    // V
    {
        float4 v = *(const float4*)(base + 2 * EMB + c4);
        __nv_bfloat162 V01, V23;
        V01.x = __float2bfloat16(v.x); V01.y = __float2bfloat16(v.y);
        V23.x = __float2bfloat16(v.z); V23.y = __float2bfloat16(v.w);
        *(__nv_bfloat162*)(g_v + o)     = V01;
        *(__nv_bfloat162*)(g_v + o + 2) = V23;
    }
}

// ---------------------------------------------------------------------------
// Tensor-core bf16 3-term-split GEMM (unchanged from round 5).
// ---------------------------------------------------------------------------
#define BK      32
#define AS_STR  40
#define TILE_E  (128 * AS_STR)

__global__ __launch_bounds__(256) void tgemm_mma(
    const float* __restrict__ bias, float* __restrict__ Cext, int N, int mode)
{
    __shared__ alignas(16) __nv_bfloat16 As[2][TILE_E];
    __shared__ alignas(16) __nv_bfloat16 Bs[2][TILE_E];

    const int tid  = threadIdx.x;
    const int wid  = tid >> 5;
    const int lane = tid & 31;
    const int wm   = wid & 1;
    const int wn   = wid >> 1;
    const int m0   = blockIdx.y * 128;
    const int n0   = blockIdx.x * 128;
    const int K    = EMB;
    const int NIT  = 96;

    const __nv_bfloat16* Bh = mode ? g_wo_hi : g_wq_hi;
    const __nv_bfloat16* Bl = mode ? g_wo_lo : g_wq_lo;
    float* C = mode ? Cext : (float*)g_qkv;

    float acc[4][4][4];
#pragma unroll
    for (int i = 0; i < 4; i++)
#pragma unroll
        for (int j = 0; j < 4; j++)
#pragma unroll
            for (int k = 0; k < 4; k++) acc[i][j][k] = 0.f;

    const int r0 = (tid * 2) >> 2,     c0 = ((tid * 2) & 3) * 8;
    const int r1 = (tid * 2 + 1) >> 2, c1 = ((tid * 2 + 1) & 3) * 8;

    const int a_lrow  = lane & 15;
    const int a_lcol  = (lane >> 4) * 8;
    const int b_lrow  = (lane & 7) + ((lane >> 4) << 3);
    const int b_lcol  = ((lane >> 3) & 1) * 8;

    const uint32_t sA = smem_u32(As);
    const uint32_t sB = smem_u32(Bs);

    {
        *(float4*)&As[0][r0 * AS_STR + c0] =
            *(const float4*)(g_a_hi + (size_t)(m0 + r0) * K + c0);
        *(float4*)&As[0][r1 * AS_STR + c1] =
            *(const float4*)(g_a_hi + (size_t)(m0 + r1) * K + c1);
        *(float4*)&Bs[0][r0 * AS_STR + c0] =
            *(const float4*)(Bh + (size_t)(n0 + r0) * K + c0);
        *(float4*)&Bs[0][r1 * AS_STR + c1] =
            *(const float4*)(Bh + (size_t)(n0 + r1) * K + c1);
    }
    __syncthreads();

    int buf = 0;
    for (int it = 0; it < NIT; it++) {
        float4 pa0, pa1, pb0, pb1;
        if (it + 1 < NIT) {
            const int nit = it + 1;
            const int seg = nit >> 5;
            const int kk  = (nit & 31) * BK;
            const __nv_bfloat16* Ap = (seg < 2)  ? g_a_hi : g_a_lo;
            const __nv_bfloat16* Bp = (seg == 1) ? Bl : Bh;
            pa0 = *(const float4*)(Ap + (size_t)(m0 + r0) * K + kk + c0);
            pa1 = *(const float4*)(Ap + (size_t)(m0 + r1) * K + kk + c1);
            pb0 = *(const float4*)(Bp + (size_t)(n0 + r0) * K + kk + c0);
            pb1 = *(const float4*)(Bp + (size_t)(n0 + r1) * K + kk + c1);
        }

        const uint32_t baseA = sA + (uint32_t)buf * (TILE_E * 2);
        const uint32_t baseB = sB + (uint32_t)buf * (TILE_E * 2);
#pragma unroll
        for (int ks = 0; ks < 2; ks++) {
            const int k8 = ks * 16;
            uint32_t a[4][4];
#pragma unroll
            for (int mf = 0; mf < 4; mf++) {
                uint32_t addr = baseA +
                    ((uint32_t)((wm * 64 + mf * 16 + a_lrow) * AS_STR
                                + k8 + a_lcol) << 1);
                ldmx4(a[mf], addr);
            }
            uint32_t b[2][4];
#pragma unroll
            for (int nf2 = 0; nf2 < 2; nf2++) {
                uint32_t addr = baseB +
                    ((uint32_t)((wn * 32 + nf2 * 16 + b_lrow) * AS_STR
                                + k8 + b_lcol) << 1);
                ldmx4(b[nf2], addr);
            }
#pragma unroll
            for (int mf = 0; mf < 4; mf++) {
#pragma unroll
                for (int nf = 0; nf < 4; nf++) {
                    uint32_t b0 = b[nf >> 1][(nf & 1) * 2];
                    uint32_t b1 = b[nf >> 1][(nf & 1) * 2 + 1];
                    mma_bf16(acc[mf][nf], a[mf], b0, b1);
                }
            }
        }

        if (it + 1 < NIT) {
            int nb = buf ^ 1;
            *(float4*)&As[nb][r0 * AS_STR + c0] = pa0;
            *(float4*)&As[nb][r1 * AS_STR + c1] = pa1;
            *(float4*)&Bs[nb][r0 * AS_STR + c0] = pb0;
            *(float4*)&Bs[nb][r1 * AS_STR + c1] = pb1;
        }
        __syncthreads();
        buf ^= 1;
    }

#pragma unroll
    for (int mf = 0; mf < 4; mf++) {
        const int r = m0 + wm * 64 + mf * 16 + (lane >> 2);
#pragma unroll
        for (int nf = 0; nf < 4; nf++) {
            const int c = n0 + wn * 32 + nf * 8 + (lane & 3) * 2;
            const float b0 = bias[c], b1 = bias[c + 1];
            float2 lo = make_float2(acc[mf][nf][0] + b0, acc[mf][nf][1] + b1);
            float2 hi = make_float2(acc[mf][nf][2] + b0, acc[mf][nf][3] + b1);
            *(float2*)&C[(size_t)r * N + c]       = lo;
            *(float2*)&C[(size_t)(r + 8) * N + c] = hi;
        }
    }
}

// ---------------------------------------------------------------------------
// Tensor-core flash attention.
// Block: (b,h) x 128-query tile; 8 warps, each owns 16 query rows.
// Key-tiles of 64. S = Qh*Kh + Ql*Kh + Qh*Kl (Q pre-scaled by 0.125).
// Online softmax per-warp (rows live in lane quads: shfl_xor 1,2 only).
// P repacked in-register (c-frag -> a-frag), V via ldmatrix.trans.
// ---------------------------------------------------------------------------
#define HPAD 72

__global__ __launch_bounds__(256) void attn_mma_kernel()
{
    __shared__ alignas(16) __nv_bfloat16 sKh[64 * HPAD];
    __shared__ alignas(16) __nv_bfloat16 sKl[64 * HPAD];
    __shared__ alignas(16) __nv_bfloat16 sV [64 * HPAD];

    const int tid  = threadIdx.x;
    const int w    = tid >> 5;
    const int lane = tid & 31;
    const int bh   = blockIdx.x;
    const int b    = bh >> 4;
    const int h    = bh & 15;
    const int q0   = blockIdx.y * 128;
    const int qoff = h * HD;
    const size_t grow0 = (size_t)(b * SEQ);

    const uint32_t aKh = smem_u32(sKh);
    const uint32_t aKl = smem_u32(sKl);
    const uint32_t aV  = smem_u32(sV);

    // ldmatrix lane addressing
    const int a_lrow = lane & 15;             // A (non-trans)
    const int a_lcol = (lane >> 4) * 8;
    const int b_lrow = (lane & 7) + ((lane >> 4) << 3);   // B (non-trans)
    const int b_lcol = ((lane >> 3) & 1) * 8;
    const int v_lrow = lane & 15;             // B (trans) for V
    const int v_lcol = (lane >> 4) * 8;

    // --- Load Q fragments (hi then lo) via smem staging in sKh/sKl region ---
    uint32_t qh[4][4], ql[4][4];
    {
        // stage Qh: 128 rows x 64 cols -> flat [r*HPAD + c] across sKh+sKl
        __nv_bfloat16* stage = sKh;
        const uint32_t aStage = aKh;
#pragma unroll
        for (int pass = 0; pass < 2; pass++) {
            const __nv_bfloat16* src = pass ? g_q_lo : g_q_hi;
            for (int u = 0; u < 4; u++) {
                int idx = tid + 256 * u;            // 0..1023
                int r = idx >> 3, c8 = (idx & 7) * 8;
                *(float4*)&stage[r * HPAD + c8] =
                    *(const float4*)(src + (grow0 + q0 + r) * EMB + qoff + c8);
            }
            __syncthreads();
            uint32_t (*dst)[4] = pass ? ql : qh;
#pragma unroll
            for (int d = 0; d < 4; d++) {
                uint32_t addr = aStage +
                    ((uint32_t)((w * 16 + a_lrow) * HPAD + d * 16 + a_lcol) << 1);
                ldmx4(dst[d], addr);
            }
            __syncthreads();
        }
    }

    float o[8][4];
#pragma unroll
    for (int i = 0; i < 8; i++)
#pragma unroll
        for (int j = 0; j < 4; j++) o[i][j] = 0.f;
    float m_lo = -1e30f, m_hi = -1e30f, l_lo = 0.f, l_hi = 0.f;

    for (int kt = 0; kt < SEQ / 64; kt++) {
        // Load Kh, Kl, V tiles (64 rows x 64 cols each)
        {
            const size_t rbase = (grow0 + kt * 64) * EMB + qoff;
#pragma unroll
            for (int u = 0; u < 2; u++) {
                int idx = tid * 2 + u;             // 0..511
                int r = idx >> 3, c8 = (idx & 7) * 8;
                size_t g = rbase + (size_t)r * EMB + c8;
                *(float4*)&sKh[r * HPAD + c8] = *(const float4*)(g_k_hi + g);
                *(float4*)&sKl[r * HPAD + c8] = *(const float4*)(g_k_lo + g);
                *(float4*)&sV [r * HPAD + c8] = *(const float4*)(g_v   + g);
            }
        }
        __syncthreads();

        // S = Qh*Kh + Ql*Kh + Qh*Kl   (16 q x 64 keys per warp)
        float s[8][4];
#pragma unroll
        for (int i = 0; i < 8; i++)
#pragma unroll
            for (int j = 0; j < 4; j++) s[i][j] = 0.f;

#pragma unroll
        for (int d = 0; d < 4; d++) {
#pragma unroll
            for (int nf2 = 0; nf2 < 4; nf2++) {
                uint32_t off = ((uint32_t)((nf2 * 16 + b_lrow) * HPAD
                                           + d * 16 + b_lcol) << 1);
                uint32_t bk[4], bl[4];
                ldmx4(bk, aKh + off);
                ldmx4(bl, aKl + off);
#pragma unroll
                for (int half = 0; half < 2; half++) {
                    float* acc = s[nf2 * 2 + half];
                    uint32_t k0 = bk[half * 2], k1 = bk[half * 2 + 1];
                    mma_bf16(acc, qh[d], k0, k1);
                    mma_bf16(acc, ql[d], k0, k1);
                    mma_bf16(acc, qh[d], bl[half * 2], bl[half * 2 + 1]);
                }
            }
        }

        // Online softmax (rows: lo = lane/4, hi = lane/4+8 of this warp's 16)
        float rmax_lo = -1e30f, rmax_hi = -1e30f;
#pragma unroll
        for (int j = 0; j < 8; j++) {
            rmax_lo = fmaxf(rmax_lo, fmaxf(s[j][0], s[j][1]));
            rmax_hi = fmaxf(rmax_hi, fmaxf(s[j][2], s[j][3]));
        }
        rmax_lo = fmaxf(rmax_lo, __shfl_xor_sync(0xffffffffu, rmax_lo, 1));
        rmax_lo = fmaxf(rmax_lo, __shfl_xor_sync(0xffffffffu, rmax_lo, 2));
        rmax_hi = fmaxf(rmax_hi, __shfl_xor_sync(0xffffffffu, rmax_hi, 1));
        rmax_hi = fmaxf(rmax_hi, __shfl_xor_sync(0xffffffffu, rmax_hi, 2));

        float mn_lo = fmaxf(m_lo, rmax_lo);
        float mn_hi = fmaxf(m_hi, rmax_hi);
        float alpha_lo = __expf(m_lo - mn_lo);
        float alpha_hi = __expf(m_hi - mn_hi);

        uint32_t pl[8], ph[8];     // packed bf16x2 P fragments
        float rs_lo = 0.f, rs_hi = 0.f;
#pragma unroll
        for (int j = 0; j < 8; j++) {
            float p0 = __expf(s[j][0] - mn_lo);
            float p1 = __expf(s[j][1] - mn_lo);
            float p2 = __expf(s[j][2] - mn_hi);
            float p3 = __expf(s[j][3] - mn_hi);
            rs_lo += p0 + p1;
            rs_hi += p2 + p3;
            pl[j] = pack_bf16x2(p0, p1);
            ph[j] = pack_bf16x2(p2, p3);
        }
        rs_lo += __shfl_xor_sync(0xffffffffu, rs_lo, 1);
        rs_lo += __shfl_xor_sync(0xffffffffu, rs_lo, 2);
        rs_hi += __shfl_xor_sync(0xffffffffu, rs_hi, 1);
        rs_hi += __shfl_xor_sync(0xffffffffu, rs_hi, 2);

        l_lo = l_lo * alpha_lo + rs_lo;
        l_hi = l_hi * alpha_hi + rs_hi;
        m_lo = mn_lo;
        m_hi = mn_hi;
#pragma unroll
        for (int nf = 0; nf < 8; nf++) {
            o[nf][0] *= alpha_lo; o[nf][1] *= alpha_lo;
            o[nf][2] *= alpha_hi; o[nf][3] *= alpha_hi;
        }

        // O += P @ V
#pragma unroll
        for (int ks = 0; ks < 4; ks++) {
            uint32_t A[4] = {pl[ks * 2], ph[ks * 2], pl[ks * 2 + 1], ph[ks * 2 + 1]};
#pragma unroll
            for (int nc = 0; nc < 4; nc++) {
                uint32_t addr = aV +
                    ((uint32_t)((ks * 16 + v_lrow) * HPAD + nc * 16 + v_lcol) << 1);
                uint32_t bv[4];
                ldmx4t(bv, addr);
                mma_bf16(o[nc * 2],     A, bv[0], bv[1]);
                mma_bf16(o[nc * 2 + 1], A, bv[2], bv[3]);
            }
        }
        __syncthreads();
    }

    // Normalize and write ctx (fp32)
    const float inv_lo = 1.0f / l_lo;
    const float inv_hi = 1.0f / l_hi;
    const size_t row_lo = grow0 + q0 + w * 16 + (lane >> 2);
    const size_t row_hi = row_lo + 8;
#pragma unroll
    for (int nf = 0; nf < 8; nf++) {
        const int c = qoff + nf * 8 + (lane & 3) * 2;
        *(float2*)&g_ctx[row_lo * EMB + c] =
            make_float2(o[nf][0] * inv_lo, o[nf][1] * inv_lo);
        *(float2*)&g_ctx[row_hi * EMB + c] =
            make_float2(o[nf][2] * inv_hi, o[nf][3] * inv_hi);
    }
}

// ---------------------------------------------------------------------------
// Launch: pure kernel launches (graph-capture safe, no runtime API calls).
// ---------------------------------------------------------------------------
extern "C" void kernel_launch(void* const* d_in, const int* in_sizes, int n_in,
                              void* d_out, int out_size)
{
    const float* x     = (const float*)d_in[0];
    const float* W_qkv = (const float*)d_in[1];
    const float* b_qkv = (const float*)d_in[2];
    const float* W_o   = (const float*)d_in[3];
    const float* b_o   = (const float*)d_in[4];
    float* out = (float*)d_out;

    const size_t n4 = (size_t)MTOT * EMB / 4;

    // Preprocess: split x, transpose+split weights
    split_kernel<<<(unsigned)((n4 + 255) / 256), 256>>>(x, 0, n4);
    transpose_split_kernel<<<dim3(E3 / 32, EMB / 32), dim3(32, 8)>>>(W_qkv, 0, EMB, E3);
    transpose_split_kernel<<<dim3(EMB / 32, EMB / 32), dim3(32, 8)>>>(W_o, 1, EMB, EMB);

    // 1) QKV projection on tensor cores -> g_qkv
    tgemm_mma<<<dim3(E3 / 128, MTOT / 128), 256>>>(b_qkv, nullptr, E3, 0);

    // 2) Convert qkv -> bf16 attention operands, run tensor-core attention
    qkv_convert_kernel<<<(unsigned)((n4 + 255) / 256), 256>>>();
    attn_mma_kernel<<<dim3(BATCH * HEADS, SEQ / 128), 256>>>();

    // 3) Split ctx, output projection on tensor cores -> d_out
    split_kernel<<<(unsigned)((n4 + 255) / 256), 256>>>(nullptr, 1, n4);
    tgemm_mma<<<dim3(EMB / 128, MTOT / 128), 256>>>(b_o, out, EMB, 1);
}